// round 10
// baseline (speedup 1.0000x reference)
#include <cuda_runtime.h>
#include <math.h>

// Problem constants
#define N1v 4000
#define N2v 4000
#define GD  8000
#define RD  20000
#define M1v 1200
#define M2v 1200
#define MGv 2400
#define MRv 6000

#define TROW 8            // rows per loss tile
#define JC   4000         // j-chunk width
// loss grid segmentation (loss3 first)
#define NB3 (5*300)       // 5 j-chunks x ceil(MGv/TROW)=300   -> 1500
#define NB2 (5*150)       // 5 j-chunks x ceil(M2v/TROW)=150   -> 750
#define NB1 (2*150)       // 2 j-chunks x ceil(M1v/TROW)=150   -> 300
#define NBT (NB3+NB2+NB1) // 2550

// ---------------- device scratch (no allocation allowed) ----------------
__device__ __align__(16) int d_hist1[N1v];
__device__ __align__(16) int d_hist2[N2v];
__device__ __align__(16) int d_histg[GD];
__device__ __align__(16) int d_histr[RD];

// dense per-column tables
__device__ float4 d_tblG[GD];   __device__ float d_wtG[GD];   // (pg, bg), cnt_g
__device__ float4 d_tblR[RD];   __device__ float d_wtR[RD];   // (pr, br), cnt_r
__device__ float4 d_zR[RD];                                    // cnt_r * pr  (loss3)

// compacted row lists (unordered; order is irrelevant for the sums)
__device__ int    d_r1o[M1v]; __device__ float4 d_r1q[M1v]; __device__ float d_r1w[M1v];
__device__ int    d_r2o[M2v]; __device__ float4 d_r2q[M2v]; __device__ float d_r2w[M2v];
__device__ int    d_rAo[MGv]; __device__ float4 d_rAp[MGv];   // cnt_g * pg
__device__ int    d_nrows[3];   // [G rows (m1), R rows (m2), A rows (mg)]
// 0: loss1, 1: loss2, 2: S (trace), 3: ||Pg||^2, 4: ||Pr||^2
__device__ double d_acc[5];

// ---------------- helpers ----------------
__device__ __forceinline__ void softmax3(float a, float b, float c,
                                         float& p0, float& p1, float& p2) {
    float m  = fmaxf(a, fmaxf(b, c));
    float e0 = __expf(a - m), e1 = __expf(b - m), e2 = __expf(c - m);
    float inv = 1.0f / (e0 + e1 + e2);
    p0 = e0 * inv; p1 = e1 * inv; p2 = e2 * inv;
}

__device__ __forceinline__ float warp_sum(float v) {
    #pragma unroll
    for (int off = 16; off > 0; off >>= 1)
        v += __shfl_down_sync(0xFFFFFFFFu, v, off);
    return v;
}

// ---------------- K1: histograms (4 concurrent blocks, no sort/scan) ------------
// Exact: every per-index quantity depends only on the mask VALUE; duplicates are
// multiplicity counts. Dense count tables make the loss pass fully streaming.
__global__ void hist_kernel(const int* __restrict__ m1, const int* __restrict__ m2,
                            const int* __restrict__ mg, const int* __restrict__ mr) {
    extern __shared__ int sh[];
    const int which = blockIdx.x;
    const int tid = threadIdx.x, bd = blockDim.x;   // 1024

    const int* in; int n, vmax; int* out;
    if      (which == 0) { in = m1; n = M1v; vmax = N1v; out = d_hist1; }
    else if (which == 1) { in = m2; n = M2v; vmax = N2v; out = d_hist2; }
    else if (which == 2) { in = mg; n = MGv; vmax = GD;  out = d_histg; }
    else                 { in = mr; n = MRv; vmax = RD;  out = d_histr; }

    if (which == 0) {     // reset accumulators + row counters each graph replay
        if (tid < 5) d_acc[tid] = 0.0;
        else if (tid < 8) d_nrows[tid - 5] = 0;
    }

    for (int v = tid; v < vmax; v += bd) sh[v] = 0;
    __syncthreads();
    for (int k = tid; k < n; k += bd) atomicAdd(&sh[in[k]], 1);
    __syncthreads();
    // vectorized dense write (all vmax are multiples of 4; arrays 16B-aligned)
    int4* o4 = reinterpret_cast<int4*>(out);
    const int4* s4 = reinterpret_cast<const int4*>(sh);
    for (int v = tid; v < vmax / 4; v += bd) o4[v] = s4[v];
}

// ---------------- K2: tables + unordered row compaction + norms -----------------
__global__ void table_kernel(const float* __restrict__ C1, const float* __restrict__ C2,
                             const float* __restrict__ Cg, const float* __restrict__ Cr,
                             const float* __restrict__ Ai, const float* __restrict__ bg,
                             const float* __restrict__ br, const float* __restrict__ b1,
                             const float* __restrict__ b2) {
    const int t = blockIdx.x * blockDim.x + threadIdx.x;
    float ng = 0.0f, nr = 0.0f;

    if (t < RD) {                               // mask_r columns
        int v = t;
        float c = (float)d_histr[v];
        float p0, p1, p2; softmax3(Cr[3*v], Cr[3*v+1], Cr[3*v+2], p0, p1, p2);
        d_tblR[v] = make_float4(p0, p1, p2, br[v]);
        d_wtR[v]  = c;
        d_zR[v]   = make_float4(c*p0, c*p1, c*p2, 0.0f);
        nr = c * (p0*p0 + p1*p1 + p2*p2);
    } else if (t < RD + GD) {                   // mask_g: columns of G AND rows of A
        int v = t - RD;
        int cnt = d_histg[v];
        float c = (float)cnt;
        float p0, p1, p2; softmax3(Cg[3*v], Cg[3*v+1], Cg[3*v+2], p0, p1, p2);
        d_tblG[v] = make_float4(p0, p1, p2, bg[v]);
        d_wtG[v]  = c;
        if (cnt) {
            int idx = atomicAdd(&d_nrows[2], 1);
            d_rAo[idx] = v * RD;
            d_rAp[idx] = make_float4(c*p0, c*p1, c*p2, 0.0f);
        }
        ng = c * (p0*p0 + p1*p1 + p2*p2);
    } else if (t < RD + GD + N1v) {             // mask_1: rows of G
        int v = t - RD - GD;
        int cnt = d_hist1[v];
        if (cnt) {
            float p0, p1, p2; softmax3(C1[3*v], C1[3*v+1], C1[3*v+2], p0, p1, p2);
            float q0 = p0*Ai[0] + p1*Ai[3] + p2*Ai[6];
            float q1 = p0*Ai[1] + p1*Ai[4] + p2*Ai[7];
            float q2 = p0*Ai[2] + p1*Ai[5] + p2*Ai[8];
            int idx = atomicAdd(&d_nrows[0], 1);
            d_r1o[idx] = v * GD;
            d_r1q[idx] = make_float4(q0, q1, q2, b1[v]);
            d_r1w[idx] = (float)cnt;
        }
    } else if (t < RD + GD + N1v + N2v) {       // mask_2: rows of R
        int v = t - RD - GD - N1v;
        int cnt = d_hist2[v];
        if (cnt) {
            float p0, p1, p2; softmax3(C2[3*v], C2[3*v+1], C2[3*v+2], p0, p1, p2);
            float q0 = p0*Ai[0] + p1*Ai[3] + p2*Ai[6];
            float q1 = p0*Ai[1] + p1*Ai[4] + p2*Ai[7];
            float q2 = p0*Ai[2] + p1*Ai[5] + p2*Ai[8];
            int idx = atomicAdd(&d_nrows[1], 1);
            d_r2o[idx] = v * RD;
            d_r2q[idx] = make_float4(q0, q1, q2, b2[v]);
            d_r2w[idx] = (float)cnt;
        }
    }

    // block-reduce the norm partials -> 2 atomics per block
    __shared__ float red_g[8], red_r[8];
    const int lane = threadIdx.x & 31, wid = threadIdx.x >> 5;
    ng = warp_sum(ng); nr = warp_sum(nr);
    if (lane == 0) { red_g[wid] = ng; red_r[wid] = nr; }
    __syncthreads();
    if (wid == 0) {
        float vg = (lane < 8) ? red_g[lane] : 0.0f;
        float vr = (lane < 8) ? red_r[lane] : 0.0f;
        #pragma unroll
        for (int off = 4; off > 0; off >>= 1) {
            vg += __shfl_down_sync(0xFFFFFFFFu, vg, off);
            vr += __shfl_down_sync(0xFFFFFFFFu, vr, off);
        }
        if (lane == 0) {
            if (vg != 0.0f) atomicAdd(&d_acc[3], (double)vg);
            if (vr != 0.0f) atomicAdd(&d_acc[4], (double)vr);
        }
    }
}

// ---------------- K3: dense streaming loss kernel (8 rows x 4000-col tiles) -----
__global__ void __launch_bounds__(256)
loss_kernel(const float* __restrict__ G, const float* __restrict__ R,
            const float* __restrict__ A) {
    __shared__ int    soff[TROW];
    __shared__ float4 srow[TROW];
    __shared__ float  swt[TROW];
    __shared__ float  red[8];
    const int tid = threadIdx.x, lane = tid & 31, wid = tid >> 5;
    int b = blockIdx.x;
    float contrib = 0.0f;
    int accIdx;

    if (b < NB3) {
        // ---- loss3: S += sum_j ( sum_k (cg*pg)_k * A[k,j] ) . (cr*pr)_j ----
        accIdx = 2;
        const int bx = b % 5, by = b / 5;
        const int row0 = by * TROW;
        const int nA = d_nrows[2];
        if (row0 >= nA) return;
        if (tid < TROW) {
            int i = row0 + tid;
            if (i < nA) { soff[tid] = d_rAo[i]; srow[tid] = d_rAp[i]; }
            else        { soff[tid] = d_rAo[row0]; srow[tid] = make_float4(0,0,0,0); }
        }
        __syncthreads();
        const int jend = bx * JC + JC;
        for (int j = bx * JC + tid; j < jend; j += 256) {
            float av[TROW];
            #pragma unroll
            for (int k = 0; k < TROW; k++) av[k] = __ldg(A + soff[k] + j);
            float4 z = d_zR[j];
            float y0 = 0.0f, y1 = 0.0f, y2 = 0.0f;
            #pragma unroll
            for (int k = 0; k < TROW; k++) {
                float4 p = srow[k];
                y0 = fmaf(av[k], p.x, y0);
                y1 = fmaf(av[k], p.y, y1);
                y2 = fmaf(av[k], p.z, y2);
            }
            contrib = fmaf(y0, z.x, fmaf(y1, z.y, fmaf(y2, z.z, contrib)));
        }
    } else {
        // ---- weighted squared-residual losses (dense columns) ----
        int u = b - NB3;
        const float* X; const float4* tbl; const float* wt;
        const int *ro; const float4 *rq; const float *rw;
        int bx, by, nRows;
        if (u < NB2) {            // loss2 over R
            X = R; tbl = d_tblR; wt = d_wtR; accIdx = 1;
            ro = d_r2o; rq = d_r2q; rw = d_r2w;
            bx = u % 5; by = u / 5; nRows = d_nrows[1];
        } else {                  // loss1 over G
            u -= NB2;
            X = G; tbl = d_tblG; wt = d_wtG; accIdx = 0;
            ro = d_r1o; rq = d_r1q; rw = d_r1w;
            bx = u % 2; by = u / 2; nRows = d_nrows[0];
        }
        const int row0 = by * TROW;
        if (row0 >= nRows) return;
        if (tid < TROW) {
            int i = row0 + tid;
            if (i < nRows) { soff[tid] = ro[i]; srow[tid] = rq[i]; swt[tid] = rw[i]; }
            else           { soff[tid] = ro[row0]; srow[tid] = make_float4(0,0,0,0);
                             swt[tid] = 0.0f; }
        }
        __syncthreads();
        const int jend = bx * JC + JC;
        for (int j = bx * JC + tid; j < jend; j += 256) {
            float gv[TROW];
            #pragma unroll
            for (int k = 0; k < TROW; k++) gv[k] = __ldg(X + soff[k] + j);
            float4 tb = tbl[j];
            float w = wt[j];
            float s = 0.0f;
            #pragma unroll
            for (int k = 0; k < TROW; k++) {
                float4 q = srow[k];
                float r = gv[k] - fmaf(q.x, tb.x, fmaf(q.y, tb.y, q.z * tb.z))
                                - tb.w - q.w;
                s = fmaf(swt[k] * r, r, s);
            }
            contrib = fmaf(w, s, contrib);
        }
    }

    // block reduce -> one double atomic per block
    contrib = warp_sum(contrib);
    if (lane == 0) red[wid] = contrib;
    __syncthreads();
    if (wid == 0) {
        float v = (lane < 8) ? red[lane] : 0.0f;
        #pragma unroll
        for (int off = 4; off > 0; off >>= 1)
            v += __shfl_down_sync(0xFFFFFFFFu, v, off);
        if (lane == 0) atomicAdd(&d_acc[accIdx], (double)v);
    }
}

// ---------------- finalize ----------------
__global__ void finalize_kernel(float* __restrict__ out) {
    double t1 = 1000.0 * (d_acc[0] / (double)((long long)M1v * MGv));
    double t2 = 1000.0 * (d_acc[1] / (double)((long long)M2v * MRv));
    double t3 = 100.0  * (-d_acc[2] / (sqrt(d_acc[3]) * sqrt(d_acc[4])));
    out[0] = (float)(t1 + t2 + t3);
    out[1] = (float)t1;
    out[2] = (float)t2;
    out[3] = (float)t3;
    out[4] = 0.0f;   // ALPHA[3] == 0 -> exactly 0
}

// ---------------- launch ----------------
extern "C" void kernel_launch(void* const* d_in, const int* in_sizes, int n_in,
                              void* d_out, int out_size) {
    const float* G  = (const float*)d_in[0];
    const float* R  = (const float*)d_in[1];
    const float* A  = (const float*)d_in[2];
    const float* C1 = (const float*)d_in[3];
    const float* C2 = (const float*)d_in[4];
    const float* Cg = (const float*)d_in[5];
    const float* Cr = (const float*)d_in[6];
    const float* Ai = (const float*)d_in[7];
    const float* bg = (const float*)d_in[8];
    const float* br = (const float*)d_in[9];
    const float* b1 = (const float*)d_in[10];
    const float* b2 = (const float*)d_in[11];
    const int* m1 = (const int*)d_in[12];
    const int* m2 = (const int*)d_in[13];
    const int* mg = (const int*)d_in[14];
    const int* mr = (const int*)d_in[15];
    float* out = (float*)d_out;

    // largest histogram (R_DIM = 20000 ints = 80 KB) exceeds default 48 KB
    cudaFuncSetAttribute(hist_kernel,
                         cudaFuncAttributeMaxDynamicSharedMemorySize,
                         RD * (int)sizeof(int));

    hist_kernel<<<4, 1024, RD * sizeof(int)>>>(m1, m2, mg, mr);

    {
        int total = RD + GD + N1v + N2v;          // 36000
        table_kernel<<<(total + 255) / 256, 256>>>(C1, C2, Cg, Cr, Ai,
                                                   bg, br, b1, b2);
    }

    loss_kernel<<<NBT, 256>>>(G, R, A);
    finalize_kernel<<<1, 32>>>(out);
}

// round 11
// speedup vs baseline: 1.1656x; 1.1656x over previous
#include <cuda_runtime.h>
#include <math.h>

// Problem constants
#define N1v 4000
#define N2v 4000
#define GD  8000
#define RD  20000
#define M1v 1200
#define M2v 1200
#define MGv 2400
#define MRv 6000

// Loss tiling (2 j-cols per thread, 512-wide tiles; one tile per block)
#define GXJ 12            // ceil(MRv/512)
#define GY3 38            // ceil(MGv/64)
#define NB3 (GXJ*GY3)     // 456
#define GY2 19            // ceil(M2v/64)
#define NB2 (GXJ*GY2)     // 228
#define GX1 5             // ceil(MGv/512)
#define GY1 38            // ceil(M1v/32)
#define NB1 (GX1*GY1)     // 190
#define NBT (NB3+NB2+NB1) // 874  == grid size (all blocks resident in one wave)

// ---------------- device scratch (no allocation allowed) ----------------
__device__ __align__(16) int d_h1[N1v];
__device__ __align__(16) int d_h2[N2v];
__device__ __align__(16) int d_hg[GD];
__device__ __align__(16) int d_hr[RD];
__device__ int    d_s1[M1v], d_s2[M2v], d_sg[MGv], d_sr[MRv];
__device__ float  d_w1[M1v], d_w2[M2v], d_wg[MGv], d_wr[MRv];
__device__ float4 d_q1[M1v], d_q2[M2v], d_pg[MGv], d_pr[MRv];
__device__ int    d_nu[4];
// 0: loss1, 1: loss2, 2: S (trace), 3: ||Pg||^2, 4: ||Pr||^2
__device__ double d_acc[5];
__device__ volatile int d_bar1, d_bar2;   // grid barriers (reset at end of each run)
__device__ int    d_done;

// ---------------- helpers ----------------
__device__ __forceinline__ void softmax3(float a, float b, float c,
                                         float& p0, float& p1, float& p2) {
    float m  = fmaxf(a, fmaxf(b, c));
    float e0 = __expf(a - m), e1 = __expf(b - m), e2 = __expf(c - m);
    float inv = 1.0f / (e0 + e1 + e2);
    p0 = e0 * inv; p1 = e1 * inv; p2 = e2 * inv;
}

__device__ __forceinline__ float warp_sum(float v) {
    #pragma unroll
    for (int off = 16; off > 0; off >>= 1)
        v += __shfl_down_sync(0xFFFFFFFFu, v, off);
    return v;
}

// Grid-wide software barrier. SAFE only because all NBT blocks are resident
// simultaneously (launch_bounds(256,6) -> 6 blocks/SM, 874 <= 6*148).
__device__ __forceinline__ void grid_bar(volatile int* bar) {
    __syncthreads();
    if (threadIdx.x == 0) {
        __threadfence();                         // release prior writes
        atomicAdd((int*)bar, 1);
        while (*bar < NBT) __nanosleep(128);     // volatile read -> L2
        __threadfence();                         // acquire
    }
    __syncthreads();
}

// ---------------- THE single fused kernel ----------------
__global__ void __launch_bounds__(256, 6)
fused_kernel(const float* __restrict__ G, const float* __restrict__ R,
             const float* __restrict__ A,
             const float* __restrict__ C1, const float* __restrict__ C2,
             const float* __restrict__ Cg, const float* __restrict__ Cr,
             const float* __restrict__ Ai, const float* __restrict__ bg,
             const float* __restrict__ br, const float* __restrict__ b1,
             const float* __restrict__ b2,
             const int* __restrict__ m1, const int* __restrict__ m2,
             const int* __restrict__ mg, const int* __restrict__ mr,
             float* __restrict__ out) {
    __shared__ float4 sq[64];
    __shared__ int    soff[64];
    __shared__ float  sw[64];
    __shared__ int    s_wsum[8];
    __shared__ float  red_a[8], red_b[8];
    const int tid = threadIdx.x, lane = tid & 31, wid = tid >> 5;
    const int b = blockIdx.x;

    // ============ PHASE 0: counting sort + dedup (blocks 0-3) ============
    // Sorting/dedup is exact: sums are permutation-invariant; duplicates ->
    // multiplicity weights. Sorted columns give quasi-coalesced gathers.
    if (b < 4) {
        const int* in; int n, vmax; int* hist; int* outv; float* outw;
        if      (b == 0) { in = m1; n = M1v; vmax = N1v; hist = d_h1; outv = d_s1; outw = d_w1; }
        else if (b == 1) { in = m2; n = M2v; vmax = N2v; hist = d_h2; outv = d_s2; outw = d_w2; }
        else if (b == 2) { in = mg; n = MGv; vmax = GD;  hist = d_hg; outv = d_sg; outw = d_wg; }
        else             { in = mr; n = MRv; vmax = RD;  hist = d_hr; outv = d_sr; outw = d_wr; }

        if (b == 0 && tid < 5) d_acc[tid] = 0.0;   // reset accumulators (pre-barrier1)

        // zero histogram (global, int4-vectorized; vmax % 4 == 0)
        for (int v = tid * 4; v < vmax; v += 1024)
            *reinterpret_cast<int4*>(hist + v) = make_int4(0, 0, 0, 0);
        __syncthreads();
        for (int k = tid; k < n; k += 256) atomicAdd(&hist[in[k]], 1);
        __syncthreads();

        const int chunk = (vmax + 255) / 256;
        const int c0 = min(tid * chunk, vmax);
        const int c1 = min(c0 + chunk, vmax);
        int cnt = 0;
        for (int v = c0; v < c1; v++) cnt += (hist[v] != 0);

        // exclusive scan of unique counts across 256 threads
        int incl = cnt;
        #pragma unroll
        for (int off = 1; off < 32; off <<= 1) {
            int t = __shfl_up_sync(0xFFFFFFFFu, incl, off);
            if (lane >= off) incl += t;
        }
        if (lane == 31) s_wsum[wid] = incl;
        __syncthreads();
        if (wid == 0 && lane < 8) {
            int s = s_wsum[lane];
            #pragma unroll
            for (int off = 1; off < 8; off <<= 1) {
                int t = __shfl_up_sync(0xFFu, s, off);
                if (lane >= off) s += t;
            }
            s_wsum[lane] = s;
        }
        __syncthreads();
        int excl = incl - cnt + (wid > 0 ? s_wsum[wid - 1] : 0);

        for (int v = c0; v < c1; v++) {
            int c = hist[v];
            if (c) { outv[excl] = v; outw[excl] = (float)c; excl++; }
        }
        if (tid == 255) d_nu[b] = excl;
    }

    grid_bar(&d_bar1);

    // ============ PHASE 1: prep (distributed; only first ~43 blocks work) ====
    {
        const int t = b * 256 + tid;
        const int nu_1 = d_nu[0], nu_2 = d_nu[1], nu_g = d_nu[2], nu_r = d_nu[3];
        float ng2 = 0.0f, nr2 = 0.0f;

        if (t < MRv) {
            if (t < nu_r) {
                int v = d_sr[t];
                float p0, p1, p2; softmax3(Cr[3*v], Cr[3*v+1], Cr[3*v+2], p0, p1, p2);
                d_pr[t] = make_float4(p0, p1, p2, br[v]);
                nr2 = d_wr[t] * (p0*p0 + p1*p1 + p2*p2);
            }
        } else if (t < MRv + MGv) {
            int j = t - MRv;
            if (j < nu_g) {
                int v = d_sg[j];
                float p0, p1, p2; softmax3(Cg[3*v], Cg[3*v+1], Cg[3*v+2], p0, p1, p2);
                d_pg[j] = make_float4(p0, p1, p2, bg[v]);
                ng2 = d_wg[j] * (p0*p0 + p1*p1 + p2*p2);
            }
        } else if (t < MRv + MGv + M1v) {
            int i = t - MRv - MGv;
            if (i < nu_1) {
                int v = d_s1[i];
                float p0, p1, p2; softmax3(C1[3*v], C1[3*v+1], C1[3*v+2], p0, p1, p2);
                float q0 = p0*Ai[0] + p1*Ai[3] + p2*Ai[6];
                float q1 = p0*Ai[1] + p1*Ai[4] + p2*Ai[7];
                float q2 = p0*Ai[2] + p1*Ai[5] + p2*Ai[8];
                d_q1[i] = make_float4(q0, q1, q2, b1[v]);
            }
        } else if (t < MRv + MGv + M1v + M2v) {
            int i = t - MRv - MGv - M1v;
            if (i < nu_2) {
                int v = d_s2[i];
                float p0, p1, p2; softmax3(C2[3*v], C2[3*v+1], C2[3*v+2], p0, p1, p2);
                float q0 = p0*Ai[0] + p1*Ai[3] + p2*Ai[6];
                float q1 = p0*Ai[1] + p1*Ai[4] + p2*Ai[7];
                float q2 = p0*Ai[2] + p1*Ai[5] + p2*Ai[8];
                d_q2[i] = make_float4(q0, q1, q2, b2[v]);
            }
        }

        float vg = warp_sum(ng2), vr = warp_sum(nr2);
        if (lane == 0) { red_a[wid] = vg; red_b[wid] = vr; }
        __syncthreads();
        if (wid == 0) {
            float xg = (lane < 8) ? red_a[lane] : 0.0f;
            float xr = (lane < 8) ? red_b[lane] : 0.0f;
            #pragma unroll
            for (int off = 4; off > 0; off >>= 1) {
                xg += __shfl_down_sync(0xFFFFFFFFu, xg, off);
                xr += __shfl_down_sync(0xFFFFFFFFu, xr, off);
            }
            if (lane == 0) {
                if (xg != 0.0f) atomicAdd(&d_acc[3], (double)xg);
                if (xr != 0.0f) atomicAdd(&d_acc[4], (double)xr);
            }
        }
    }

    grid_bar(&d_bar2);

    // ============ PHASE 2: loss tile b (2 j-cols per thread) ============
    {
        const int nu1 = d_nu[0], nu2 = d_nu[1], nug = d_nu[2], nur = d_nu[3];
        float part = 0.0f;
        int accIdx = 0;

        if (b < NB3) {
            // ---- loss3: S += w_i w_j * (pg_i . pr_j) * A[sg_i, sr_j] ----
            accIdx = 2;
            const int bx = b % GXJ, by = b / GXJ;
            const int i0 = by * 64, jb = bx * 512;
            if (i0 < nug && jb < nur) {
                if (tid < 64) {
                    int i = i0 + tid;
                    if (i < nug) {
                        float4 p = d_pg[i]; float w = d_wg[i];
                        sq[tid] = make_float4(p.x * w, p.y * w, p.z * w, 0.0f);
                        soff[tid] = d_sg[i] * RD;
                    }
                }
                __syncthreads();
                const int j0 = jb + tid, j1 = j0 + 256;
                const bool v0 = j0 < nur, v1 = j1 < nur;
                const int   c0 = v0 ? d_sr[j0] : 0;
                const int   c1 = v1 ? d_sr[j1] : 0;
                const float4 p0 = v0 ? d_pr[j0] : make_float4(0,0,0,0);
                const float4 p1 = v1 ? d_pr[j1] : make_float4(0,0,0,0);
                const float w0 = v0 ? d_wr[j0] : 0.0f;
                const float w1 = v1 ? d_wr[j1] : 0.0f;
                float a0=0,a1=0,a2=0, e0=0,e1=0,e2=0;
                const int ilim = min(64, nug - i0);
                #pragma unroll 4
                for (int i = 0; i < ilim; i++) {
                    int off = soff[i];
                    float av = __ldg(A + off + c0);
                    float bv = __ldg(A + off + c1);
                    float4 g = sq[i];
                    a0 = fmaf(av, g.x, a0); a1 = fmaf(av, g.y, a1); a2 = fmaf(av, g.z, a2);
                    e0 = fmaf(bv, g.x, e0); e1 = fmaf(bv, g.y, e1); e2 = fmaf(bv, g.z, e2);
                }
                part = (a0*p0.x + a1*p0.y + a2*p0.z) * w0
                     + (e0*p1.x + e1*p1.y + e2*p1.z) * w1;
            }
        } else {
            // ---- weighted squared-residual losses ----
            const float* X; int ld, TI, bx, by, nu_i, nu_j;
            const int *si, *sj; const float *wiA, *wjA; const float4 *qA, *pA;
            int u = b - NB3;
            if (u < NB2) {          // loss2 over R
                X = R; ld = RD; TI = 64; bx = u % GXJ; by = u / GXJ;
                nu_i = nu2; nu_j = nur; accIdx = 1;
                si = d_s2; wiA = d_w2; qA = d_q2; sj = d_sr; wjA = d_wr; pA = d_pr;
            } else {                // loss1 over G
                u -= NB2;
                X = G; ld = GD; TI = 32; bx = u % GX1; by = u / GX1;
                nu_i = nu1; nu_j = nug; accIdx = 0;
                si = d_s1; wiA = d_w1; qA = d_q1; sj = d_sg; wjA = d_wg; pA = d_pg;
            }
            const int i0 = by * TI, jb = bx * 512;
            if (i0 < nu_i && jb < nu_j) {
                if (tid < TI) {
                    int i = i0 + tid;
                    if (i < nu_i) { sq[tid] = qA[i]; soff[tid] = si[i] * ld; sw[tid] = wiA[i]; }
                }
                __syncthreads();
                const int j0 = jb + tid, j1 = j0 + 256;
                const bool v0 = j0 < nu_j, v1 = j1 < nu_j;
                const int   c0 = v0 ? sj[j0] : 0;
                const int   c1 = v1 ? sj[j1] : 0;
                const float4 p0 = v0 ? pA[j0] : make_float4(0,0,0,0);
                const float4 p1 = v1 ? pA[j1] : make_float4(0,0,0,0);
                const float w0 = v0 ? wjA[j0] : 0.0f;
                const float w1 = v1 ? wjA[j1] : 0.0f;
                float accA = 0.0f, accB = 0.0f;
                const int ilim = min(TI, nu_i - i0);
                #pragma unroll 4
                for (int i = 0; i < ilim; i++) {
                    float4 qi = sq[i];
                    int off = soff[i];
                    float wi = sw[i];
                    float gA = __ldg(X + off + c0);
                    float gB = __ldg(X + off + c1);
                    float rA = gA - fmaf(qi.x, p0.x, fmaf(qi.y, p0.y, qi.z * p0.z))
                                  - p0.w - qi.w;
                    float rB = gB - fmaf(qi.x, p1.x, fmaf(qi.y, p1.y, qi.z * p1.z))
                                  - p1.w - qi.w;
                    accA = fmaf(wi * rA, rA, accA);
                    accB = fmaf(wi * rB, rB, accB);
                }
                part = accA * w0 + accB * w1;
            }
        }

        part = warp_sum(part);
        if (lane == 0) red_a[wid] = part;
        __syncthreads();
        if (wid == 0) {
            float v = (lane < 8) ? red_a[lane] : 0.0f;
            #pragma unroll
            for (int off = 4; off > 0; off >>= 1)
                v += __shfl_down_sync(0xFFFFFFFFu, v, off);
            if (lane == 0) atomicAdd(&d_acc[accIdx], (double)v);
        }
    }

    // ============ finalize: last block writes out + resets barriers ============
    if (tid == 0) {
        __threadfence();
        int prev = atomicAdd(&d_done, 1);
        if (prev == NBT - 1) {
            double a0 = atomicAdd(&d_acc[0], 0.0);
            double a1 = atomicAdd(&d_acc[1], 0.0);
            double a2 = atomicAdd(&d_acc[2], 0.0);
            double a3 = atomicAdd(&d_acc[3], 0.0);
            double a4 = atomicAdd(&d_acc[4], 0.0);
            double t1 = 1000.0 * (a0 / (double)((long long)M1v * MGv));
            double t2 = 1000.0 * (a1 / (double)((long long)M2v * MRv));
            double t3 = 100.0  * (-a2 / (sqrt(a3) * sqrt(a4)));
            out[0] = (float)(t1 + t2 + t3);
            out[1] = (float)t1;
            out[2] = (float)t2;
            out[3] = (float)t3;
            out[4] = 0.0f;           // ALPHA[3] == 0 -> exactly 0
            // reset state for the next graph replay (we are the last worker)
            d_bar1 = 0; d_bar2 = 0; d_done = 0;
            __threadfence();
        }
    }
}

// ---------------- launch ----------------
extern "C" void kernel_launch(void* const* d_in, const int* in_sizes, int n_in,
                              void* d_out, int out_size) {
    const float* G  = (const float*)d_in[0];
    const float* R  = (const float*)d_in[1];
    const float* A  = (const float*)d_in[2];
    const float* C1 = (const float*)d_in[3];
    const float* C2 = (const float*)d_in[4];
    const float* Cg = (const float*)d_in[5];
    const float* Cr = (const float*)d_in[6];
    const float* Ai = (const float*)d_in[7];
    const float* bg = (const float*)d_in[8];
    const float* br = (const float*)d_in[9];
    const float* b1 = (const float*)d_in[10];
    const float* b2 = (const float*)d_in[11];
    const int* m1 = (const int*)d_in[12];
    const int* m2 = (const int*)d_in[13];
    const int* mg = (const int*)d_in[14];
    const int* mr = (const int*)d_in[15];
    float* out = (float*)d_out;

    fused_kernel<<<NBT, 256>>>(G, R, A, C1, C2, Cg, Cr, Ai,
                               bg, br, b1, b2, m1, m2, mg, mr, out);
}

// round 14
// speedup vs baseline: 1.3096x; 1.1235x over previous
#include <cuda_runtime.h>
#include <math.h>

// Problem constants
#define N1v 4000
#define N2v 4000
#define GD  8000
#define RD  20000
#define M1v 1200
#define M2v 1200
#define MGv 2400
#define MRv 6000

// Loss tiling: 2 j-columns per thread, 512-wide j-tiles -> 874 blocks (single wave)
#define GXJ 12            // ceil(MRv/512)
#define GY3 38            // ceil(MGv/64)
#define NB3 (GXJ*GY3)     // 456
#define GY2 19            // ceil(M2v/64)
#define NB2 (GXJ*GY2)     // 228
#define GX1 5             // ceil(MGv/512)
#define GY1 38            // ceil(M1v/32)
#define NB1 (GX1*GY1)     // 190
#define NBT (NB3+NB2+NB1) // 874

// ---------------- device scratch (no allocation allowed) ----------------
__device__ int    d_s1[M1v], d_s2[M2v], d_sg[MGv], d_sr[MRv];
__device__ float  d_w1[M1v], d_w2[M2v], d_wg[MGv], d_wr[MRv];
__device__ float4 d_q1[M1v], d_q2[M2v], d_pg[MGv], d_pr[MRv];
__device__ int    d_nu[4];      // unique counts: [m1, m2, mg, mr]
// 0: loss1, 1: loss2, 2: S (trace), 3: ||Pg||^2, 4: ||Pr||^2
__device__ double d_acc[5];

// ---------------- helpers ----------------
__device__ __forceinline__ void softmax3(float a, float b, float c,
                                         float& p0, float& p1, float& p2) {
    float m  = fmaxf(a, fmaxf(b, c));
    float e0 = __expf(a - m), e1 = __expf(b - m), e2 = __expf(c - m);
    float inv = 1.0f / (e0 + e1 + e2);
    p0 = e0 * inv; p1 = e1 * inv; p2 = e2 * inv;
}

__device__ __forceinline__ float warp_sum(float v) {
    #pragma unroll
    for (int off = 16; off > 0; off >>= 1)
        v += __shfl_down_sync(0xFFFFFFFFu, v, off);
    return v;
}

// ---------------- counting sort + dedup (4 concurrent blocks, smem histogram) ----
// Sorting/dedup is exact: all sums are permutation-invariant and every per-index
// quantity depends only on the mask VALUE; duplicates -> multiplicity weights.
// Sorted unique column values give quasi-coalesced gathers in the loss kernel.
__global__ void sort_kernel(const int* __restrict__ m1, const int* __restrict__ m2,
                            const int* __restrict__ mg, const int* __restrict__ mr) {
    extern __shared__ int sh[];           // per-block histogram (up to RD ints)
    __shared__ int wsum[32];
    const int which = blockIdx.x;
    const int tid = threadIdx.x, bd = blockDim.x;   // bd == 1024
    const int lane = tid & 31, wid = tid >> 5;

    const int* in; int n, vmax; int* outv; float* outw;
    if      (which == 0) { in = m1; n = M1v; vmax = N1v; outv = d_s1; outw = d_w1; }
    else if (which == 1) { in = m2; n = M2v; vmax = N2v; outv = d_s2; outw = d_w2; }
    else if (which == 2) { in = mg; n = MGv; vmax = GD;  outv = d_sg; outw = d_wg; }
    else                 { in = mr; n = MRv; vmax = RD;  outv = d_sr; outw = d_wr; }

    if (which == 0 && tid < 5) d_acc[tid] = 0.0;   // reset accumulators each replay

    // zero histogram (int4-vectorized; vmax % 4 == 0, extern smem is 16B aligned)
    {
        int4* s4 = reinterpret_cast<int4*>(sh);
        for (int v = tid; v < vmax / 4; v += bd) s4[v] = make_int4(0, 0, 0, 0);
    }
    __syncthreads();
    for (int k = tid; k < n; k += bd) atomicAdd(&sh[in[k]], 1);
    __syncthreads();

    const int chunk = (vmax + bd - 1) / bd;
    const int c0 = min(tid * chunk, vmax);
    const int c1 = min(c0 + chunk, vmax);
    int cnt = 0;                                   // # unique values in my chunk
    for (int v = c0; v < c1; v++) cnt += (sh[v] != 0);

    // exclusive scan of cnt across 1024 threads via warp shuffles
    int incl = cnt;
    #pragma unroll
    for (int off = 1; off < 32; off <<= 1) {
        int t = __shfl_up_sync(0xFFFFFFFFu, incl, off);
        if (lane >= off) incl += t;
    }
    if (lane == 31) wsum[wid] = incl;
    __syncthreads();
    if (wid == 0) {
        int s = wsum[lane];
        #pragma unroll
        for (int off = 1; off < 32; off <<= 1) {
            int t = __shfl_up_sync(0xFFFFFFFFu, s, off);
            if (lane >= off) s += t;
        }
        wsum[lane] = s;
    }
    __syncthreads();
    int excl = incl - cnt + (wid > 0 ? wsum[wid - 1] : 0);

    for (int v = c0; v < c1; v++) {
        int c = sh[v];
        if (c) { outv[excl] = v; outw[excl] = (float)c; excl++; }
    }
    if (tid == bd - 1) d_nu[which] = excl;
}

// ---------------- prep: softmax tables, Q = P@Ai, biases, weighted norms --------
__global__ void prep_kernel(const float* __restrict__ C1, const float* __restrict__ C2,
                            const float* __restrict__ Cg, const float* __restrict__ Cr,
                            const float* __restrict__ Ai, const float* __restrict__ bg,
                            const float* __restrict__ br, const float* __restrict__ b1,
                            const float* __restrict__ b2) {
    const int t = blockIdx.x * blockDim.x + threadIdx.x;
    const int nu_1 = d_nu[0], nu_2 = d_nu[1], nu_g = d_nu[2], nu_r = d_nu[3];
    float ng2 = 0.0f, nr2 = 0.0f;

    if (t < MRv) {
        if (t < nu_r) {
            int v = d_sr[t];
            float p0, p1, p2; softmax3(Cr[3*v], Cr[3*v+1], Cr[3*v+2], p0, p1, p2);
            d_pr[t] = make_float4(p0, p1, p2, br[v]);
            nr2 = d_wr[t] * (p0*p0 + p1*p1 + p2*p2);
        }
    } else if (t < MRv + MGv) {
        int j = t - MRv;
        if (j < nu_g) {
            int v = d_sg[j];
            float p0, p1, p2; softmax3(Cg[3*v], Cg[3*v+1], Cg[3*v+2], p0, p1, p2);
            d_pg[j] = make_float4(p0, p1, p2, bg[v]);
            ng2 = d_wg[j] * (p0*p0 + p1*p1 + p2*p2);
        }
    } else if (t < MRv + MGv + M1v) {
        int i = t - MRv - MGv;
        if (i < nu_1) {
            int v = d_s1[i];
            float p0, p1, p2; softmax3(C1[3*v], C1[3*v+1], C1[3*v+2], p0, p1, p2);
            float q0 = p0*Ai[0] + p1*Ai[3] + p2*Ai[6];
            float q1 = p0*Ai[1] + p1*Ai[4] + p2*Ai[7];
            float q2 = p0*Ai[2] + p1*Ai[5] + p2*Ai[8];
            d_q1[i] = make_float4(q0, q1, q2, b1[v]);
        }
    } else if (t < MRv + MGv + M1v + M2v) {
        int i = t - MRv - MGv - M1v;
        if (i < nu_2) {
            int v = d_s2[i];
            float p0, p1, p2; softmax3(C2[3*v], C2[3*v+1], C2[3*v+2], p0, p1, p2);
            float q0 = p0*Ai[0] + p1*Ai[3] + p2*Ai[6];
            float q1 = p0*Ai[1] + p1*Ai[4] + p2*Ai[7];
            float q2 = p0*Ai[2] + p1*Ai[5] + p2*Ai[8];
            d_q2[i] = make_float4(q0, q1, q2, b2[v]);
        }
    }

    __shared__ float rg[256], rr[256];
    const int tid = threadIdx.x;
    rg[tid] = ng2; rr[tid] = nr2;
    __syncthreads();
    for (int s = 128; s > 0; s >>= 1) {
        if (tid < s) { rg[tid] += rg[tid + s]; rr[tid] += rr[tid + s]; }
        __syncthreads();
    }
    if (tid == 0) {
        if (rg[0] != 0.0f) atomicAdd(&d_acc[3], (double)rg[0]);
        if (rr[0] != 0.0f) atomicAdd(&d_acc[4], (double)rr[0]);
    }
}

// ---------------- loss kernel: static grid, single wave, 2 j-cols/thread --------
__global__ void __launch_bounds__(256)
loss_kernel(const float* __restrict__ G, const float* __restrict__ R,
            const float* __restrict__ A) {
    __shared__ float4 sq[64];
    __shared__ int    soff[64];
    __shared__ float  sw[64];
    __shared__ float  red[8];
    const int tid = threadIdx.x, lane = tid & 31, wid = tid >> 5;
    int b = blockIdx.x;

    const int nu1 = d_nu[0], nu2 = d_nu[1], nug = d_nu[2], nur = d_nu[3];
    float part = 0.0f;
    int accIdx;

    if (b < NB3) {
        // ---- loss3: S += w_i w_j * (pg_i . pr_j) * A[sg_i, sr_j] ----
        accIdx = 2;
        const int bx = b % GXJ, by = b / GXJ;
        const int i0 = by * 64, jb = bx * 512;
        if (i0 < nug && jb < nur) {
            if (tid < 64) {
                int i = i0 + tid;
                if (i < nug) {
                    float4 p = d_pg[i]; float w = d_wg[i];
                    sq[tid] = make_float4(p.x * w, p.y * w, p.z * w, 0.0f);
                    soff[tid] = d_sg[i] * RD;
                }
            }
            __syncthreads();
            const int j0 = jb + tid, j1 = j0 + 256;
            const bool v0 = j0 < nur, v1 = j1 < nur;
            const int   c0 = v0 ? d_sr[j0] : 0;
            const int   c1 = v1 ? d_sr[j1] : 0;
            const float4 p0 = v0 ? d_pr[j0] : make_float4(0,0,0,0);
            const float4 p1 = v1 ? d_pr[j1] : make_float4(0,0,0,0);
            const float w0 = v0 ? d_wr[j0] : 0.0f;
            const float w1 = v1 ? d_wr[j1] : 0.0f;
            float a0=0,a1=0,a2=0, e0=0,e1=0,e2=0;
            const int ilim = min(64, nug - i0);
            #pragma unroll 8
            for (int i = 0; i < ilim; i++) {
                int off = soff[i];
                float av = __ldg(A + off + c0);
                float bv = __ldg(A + off + c1);
                float4 g = sq[i];
                a0 = fmaf(av, g.x, a0); a1 = fmaf(av, g.y, a1); a2 = fmaf(av, g.z, a2);
                e0 = fmaf(bv, g.x, e0); e1 = fmaf(bv, g.y, e1); e2 = fmaf(bv, g.z, e2);
            }
            part = (a0*p0.x + a1*p0.y + a2*p0.z) * w0
                 + (e0*p1.x + e1*p1.y + e2*p1.z) * w1;
        }
    } else {
        // ---- weighted squared-residual losses ----
        const float* X; int ld, TI, bx, by, nu_i, nu_j;
        const int *si, *sj; const float *wiA, *wjA; const float4 *qA, *pA;
        int u = b - NB3;
        if (u < NB2) {          // loss2 over R
            X = R; ld = RD; TI = 64; bx = u % GXJ; by = u / GXJ;
            nu_i = nu2; nu_j = nur; accIdx = 1;
            si = d_s2; wiA = d_w2; qA = d_q2; sj = d_sr; wjA = d_wr; pA = d_pr;
        } else {                // loss1 over G
            u -= NB2;
            X = G; ld = GD; TI = 32; bx = u % GX1; by = u / GX1;
            nu_i = nu1; nu_j = nug; accIdx = 0;
            si = d_s1; wiA = d_w1; qA = d_q1; sj = d_sg; wjA = d_wg; pA = d_pg;
        }
        const int i0 = by * TI, jb = bx * 512;
        if (i0 < nu_i && jb < nu_j) {
            if (tid < TI) {
                int i = i0 + tid;
                if (i < nu_i) { sq[tid] = qA[i]; soff[tid] = si[i] * ld; sw[tid] = wiA[i]; }
            }
            __syncthreads();
            const int j0 = jb + tid, j1 = j0 + 256;
            const bool v0 = j0 < nu_j, v1 = j1 < nu_j;
            const int   c0 = v0 ? sj[j0] : 0;
            const int   c1 = v1 ? sj[j1] : 0;
            const float4 p0 = v0 ? pA[j0] : make_float4(0,0,0,0);
            const float4 p1 = v1 ? pA[j1] : make_float4(0,0,0,0);
            const float w0 = v0 ? wjA[j0] : 0.0f;
            const float w1 = v1 ? wjA[j1] : 0.0f;
            float accA = 0.0f, accB = 0.0f;
            const int ilim = min(TI, nu_i - i0);
            #pragma unroll 8
            for (int i = 0; i < ilim; i++) {
                float4 qi = sq[i];
                int off = soff[i];
                float wi = sw[i];
                float gA = __ldg(X + off + c0);
                float gB = __ldg(X + off + c1);
                float rA = gA - fmaf(qi.x, p0.x, fmaf(qi.y, p0.y, qi.z * p0.z))
                              - p0.w - qi.w;
                float rB = gB - fmaf(qi.x, p1.x, fmaf(qi.y, p1.y, qi.z * p1.z))
                              - p1.w - qi.w;
                accA = fmaf(wi * rA, rA, accA);
                accB = fmaf(wi * rB, rB, accB);
            }
            part = accA * w0 + accB * w1;
        }
    }

    // warp-shuffle block reduction -> one double atomic per block
    part = warp_sum(part);
    if (lane == 0) red[wid] = part;
    __syncthreads();
    if (wid == 0) {
        float v = (lane < 8) ? red[lane] : 0.0f;
        #pragma unroll
        for (int off = 4; off > 0; off >>= 1)
            v += __shfl_down_sync(0xFFFFFFFFu, v, off);
        if (lane == 0) atomicAdd(&d_acc[accIdx], (double)v);
    }
}

// ---------------- finalize ----------------
__global__ void finalize_kernel(float* __restrict__ out) {
    double t1 = 1000.0 * (d_acc[0] / (double)((long long)M1v * MGv));
    double t2 = 1000.0 * (d_acc[1] / (double)((long long)M2v * MRv));
    double t3 = 100.0  * (-d_acc[2] / (sqrt(d_acc[3]) * sqrt(d_acc[4])));
    out[0] = (float)(t1 + t2 + t3);
    out[1] = (float)t1;
    out[2] = (float)t2;
    out[3] = (float)t3;
    out[4] = 0.0f;   // ALPHA[3] == 0 -> exactly 0
}

// ---------------- launch ----------------
extern "C" void kernel_launch(void* const* d_in, const int* in_sizes, int n_in,
                              void* d_out, int out_size) {
    const float* G  = (const float*)d_in[0];
    const float* R  = (const float*)d_in[1];
    const float* A  = (const float*)d_in[2];
    const float* C1 = (const float*)d_in[3];
    const float* C2 = (const float*)d_in[4];
    const float* Cg = (const float*)d_in[5];
    const float* Cr = (const float*)d_in[6];
    const float* Ai = (const float*)d_in[7];
    const float* bg = (const float*)d_in[8];
    const float* br = (const float*)d_in[9];
    const float* b1 = (const float*)d_in[10];
    const float* b2 = (const float*)d_in[11];
    const int* m1 = (const int*)d_in[12];
    const int* m2 = (const int*)d_in[13];
    const int* mg = (const int*)d_in[14];
    const int* mr = (const int*)d_in[15];
    float* out = (float*)d_out;

    // largest histogram (R_DIM = 20000 ints = 80 KB) exceeds default 48 KB
    cudaFuncSetAttribute(sort_kernel,
                         cudaFuncAttributeMaxDynamicSharedMemorySize,
                         RD * (int)sizeof(int));

    sort_kernel<<<4, 1024, RD * sizeof(int)>>>(m1, m2, mg, mr);

    {
        int total = MRv + MGv + M1v + M2v;          // 10800
        prep_kernel<<<(total + 255) / 256, 256>>>(C1, C2, Cg, Cr, Ai, bg, br, b1, b2);
    }

    loss_kernel<<<NBT, 256>>>(G, R, A);
    finalize_kernel<<<1, 32>>>(out);
}